// round 3
// baseline (speedup 1.0000x reference)
#include <cuda_runtime.h>

#define H 768
#define NWARP 1024          // warps in each fused pass
#define JPL 24              // columns per lane: 768 / 32

// ---------------- scratch (__device__ globals: allocation-free) ----------------
__device__ float g_colmax[H];        // fact_Q
__device__ float g_qw[H];            // fact_Q @ W
__device__ float g_ep[H];            // elements_p_
__device__ float g_fact[H];          // fact_
__device__ float g_v[H];             // W @ elements_p_
__device__ float g_pm[NWARP];        // per-warp running max
__device__ float g_ps[NWARP];        // per-warp running sum
__device__ float g_coef[NWARP];      // exp(m_w - M)/S
__device__ float g_pacc[(size_t)NWARP * H];  // per-warp weighted accumulators (3 MB)

// ---------------- helpers ----------------
__device__ __forceinline__ void atomicMaxFloat(float* addr, float val) {
    // sign trick: works with addr initialized to -inf (0xff800000)
    if (val >= 0.0f)
        atomicMax((int*)addr, __float_as_int(val));
    else
        atomicMin((unsigned int*)addr, __float_as_uint(val));
}

__device__ __forceinline__ float warpReduceSum(float v) {
    #pragma unroll
    for (int o = 16; o; o >>= 1) v += __shfl_xor_sync(0xffffffffu, v, o);
    return v;
}

// ---------------- kernels ----------------

// zero / -inf init of accumulators (idempotent per launch → deterministic replays)
__global__ void init_kernel() {
    int t = threadIdx.x;   // 768 threads
    g_colmax[t] = __int_as_float(0xff800000);
    g_qw[t] = 0.0f;
    g_ep[t] = 0.0f;
    g_fact[t] = 0.0f;
}

// column max over fact [N, H]
__global__ void colmax_kernel(const float* __restrict__ fact, int N) {
    int t = threadIdx.x;  // 256
    float m0 = __int_as_float(0xff800000);
    float m1 = m0, m2 = m0;
    #pragma unroll 4
    for (int n = blockIdx.x; n < N; n += gridDim.x) {
        const float* r = fact + (size_t)n * H;
        m0 = fmaxf(m0, r[t]);
        m1 = fmaxf(m1, r[t + 256]);
        m2 = fmaxf(m2, r[t + 512]);
    }
    atomicMaxFloat(&g_colmax[t], m0);
    atomicMaxFloat(&g_colmax[t + 256], m1);
    atomicMaxFloat(&g_colmax[t + 512], m2);
}

// qw[j] = sum_h colmax[h] * W[h, j]   -- grid (3, 24): 3 column blocks x 24 h-chunks of 32
__global__ void qw_kernel(const float* __restrict__ W) {
    int j  = blockIdx.x * 256 + threadIdx.x;
    int h0 = blockIdx.y * 32;
    float a = 0.0f;
    #pragma unroll 8
    for (int i = 0; i < 32; i++)
        a += g_colmax[h0 + i] * W[(size_t)(h0 + i) * H + j];
    atomicAdd(&g_qw[j], a);
}

// v[h] = sum_j W[h, j] * ep_[j]   -- one warp per row h; 96 blocks x 256 thr
__global__ void v_kernel(const float* __restrict__ W) {
    int warp = blockIdx.x * 8 + (threadIdx.x >> 5);
    int lane = threadIdx.x & 31;
    const float* row = W + (size_t)warp * H;
    float p = 0.0f;
    #pragma unroll
    for (int j = 0; j < JPL; j++)
        p += row[lane + 32 * j] * g_ep[lane + 32 * j];
    p = warpReduceSum(p);
    if (lane == 0) g_v[warp] = p;
}

// Fused: per row r of X: d = X[r]·v ; online softmax over rows with
// vector accumulation acc += exp(d - m) * X[r].  One warp per row-group.
// USE_V: true -> v = g_v (fact pass), false -> v = g_qw (elements pass)
template <bool USE_V>
__global__ void __launch_bounds__(256)
fused_softmax_wsum(const float* __restrict__ X, int rows_per_warp) {
    const float* vsrc = USE_V ? g_v : g_qw;
    int warp = (blockIdx.x * blockDim.x + threadIdx.x) >> 5;
    int lane = threadIdx.x & 31;
    size_t row0 = (size_t)warp * rows_per_warp;

    float vr[JPL], acc[JPL];
    #pragma unroll
    for (int j = 0; j < JPL; j++) { vr[j] = vsrc[lane + 32 * j]; acc[j] = 0.0f; }

    float m = __int_as_float(0xff800000);
    float s = 0.0f;

    for (int r = 0; r < rows_per_warp; r++) {
        const float* xr = X + (row0 + r) * H;
        float val[JPL];
        float p = 0.0f;
        #pragma unroll
        for (int j = 0; j < JPL; j++) {
            val[j] = xr[lane + 32 * j];
            p += val[j] * vr[j];
        }
        p = warpReduceSum(p);           // full dot, all lanes hold it

        if (p > m) {                    // rescale running state
            float sc = __expf(m - p);   // exp(-inf)=0 on first row
            s *= sc;
            #pragma unroll
            for (int j = 0; j < JPL; j++) acc[j] *= sc;
            m = p;
        }
        float w = __expf(p - m);
        s += w;
        #pragma unroll
        for (int j = 0; j < JPL; j++) acc[j] += w * val[j];
    }

    if (lane == 0) { g_pm[warp] = m; g_ps[warp] = s; }
    #pragma unroll
    for (int j = 0; j < JPL; j++)
        g_pacc[(size_t)warp * H + lane + 32 * j] = acc[j];
}

// single block: global max M, S = sum exp(m_w - M) * s_w, coef[w] = exp(m_w - M)/S
__global__ void merge_ms_kernel() {
    __shared__ float sh[NWARP];
    int t = threadIdx.x;   // 1024
    float mw = g_pm[t];
    sh[t] = mw;
    __syncthreads();
    for (int o = 512; o; o >>= 1) { if (t < o) sh[t] = fmaxf(sh[t], sh[t + o]); __syncthreads(); }
    float M = sh[0];
    __syncthreads();
    float e = __expf(mw - M);
    sh[t] = e * g_ps[t];
    __syncthreads();
    for (int o = 512; o; o >>= 1) { if (t < o) sh[t] += sh[t + o]; __syncthreads(); }
    float S = sh[0];
    g_coef[t] = e / S;
}

// out[h] += sum_w coef[w] * pacc[w][h]  -- grid (3 col-blocks, 16 warp-chunks of 64)
template <bool TO_FACT>
__global__ void merge_acc_kernel() {
    int h  = blockIdx.x * 256 + threadIdx.x;
    int w0 = blockIdx.y * (NWARP / 16);
    float a = 0.0f;
    for (int i = 0; i < NWARP / 16; i++) {
        int w = w0 + i;
        a += g_coef[w] * g_pacc[(size_t)w * H + h];
    }
    atomicAdd((TO_FACT ? g_fact : g_ep) + h, a);
}

// d_out[0:768] = fact_, d_out[768:1536] = elements_p_
__global__ void copyout_kernel(float* __restrict__ out, int out_size) {
    int i = blockIdx.x * blockDim.x + threadIdx.x;
    if (i >= out_size) return;
    out[i] = (i < H) ? g_fact[i] : g_ep[i - H];
}

// ---------------- launch ----------------
extern "C" void kernel_launch(void* const* d_in, const int* in_sizes, int n_in,
                              void* d_out, int out_size) {
    const float *fact = nullptr, *ep = nullptr, *W = nullptr;
    int N = 0, M = 0;
    for (int i = 0; i < n_in; i++) {
        long long sz = in_sizes[i];
        if (sz == (long long)H * H)            W    = (const float*)d_in[i];
        else if (sz == (long long)4096 * H)  { ep   = (const float*)d_in[i]; M = 4096; }
        else                                 { fact = (const float*)d_in[i]; N = (int)(sz / H); }
    }
    float* out = (float*)d_out;

    init_kernel<<<1, 768>>>();
    colmax_kernel<<<1024, 256>>>(fact, N);                 // pass 1 over fact (96 MB)
    qw_kernel<<<dim3(3, 24), 256>>>(W);                    // qw = fact_Q @ W

    fused_softmax_wsum<false><<<NWARP / 8, 256>>>(ep, M / NWARP);   // elements pass (12 MB)
    merge_ms_kernel<<<1, NWARP>>>();
    merge_acc_kernel<false><<<dim3(3, 16), 256>>>();       // -> g_ep

    v_kernel<<<96, 256>>>(W);                              // v = W @ ep_

    fused_softmax_wsum<true><<<NWARP / 8, 256>>>(fact, N / NWARP);  // pass 2 over fact
    merge_ms_kernel<<<1, NWARP>>>();
    merge_acc_kernel<true><<<dim3(3, 16), 256>>>();        // -> g_fact

    copyout_kernel<<<(out_size + 255) / 256, 256>>>(out, out_size);
}